// round 8
// baseline (speedup 1.0000x reference)
#include <cuda_runtime.h>
#include <cstdint>

#define Hh 576
#define Ww 640
#define HW (Hh*Ww)
#define BIGF 1e10f
#define EPSF 1e-5f

#define GRID 740            // 148 SMs x 5 blocks/SM guaranteed co-resident (regs<=51)
#define BT   256
#define NTHR (GRID*BT)

// ---- scratch (__device__ globals; zero-initialized at module load) ----
// Depth keys: key = ~bits(z); z>0 => key>0x80000000; key==0 means empty.
// min(z) = decode(max key). Phase 3 resets keys to 0 => replay invariant.
__device__ unsigned int g_depth_key[HW];
__device__ float        g_patchmin[HW];
__device__ float4       g_acc4[HW];
__device__ unsigned int g_bar_arrive;   // self-resetting each barrier
__device__ unsigned int g_bar_gen;      // monotone generation counter

__device__ __forceinline__ void red_add_v4(float4* p, float a, float b, float c, float d) {
    asm volatile("red.global.add.v4.f32 [%0], {%1,%2,%3,%4};"
                 :: "l"(__cvta_generic_to_global(p)),
                    "f"(a), "f"(b), "f"(c), "f"(d) : "memory");
}
__device__ __forceinline__ void red_add_f32(float* p, float v) {
    asm volatile("red.global.add.f32 [%0], %1;"
                 :: "l"(__cvta_generic_to_global(p)), "f"(v) : "memory");
}

// sense-reversing grid barrier; TIGHT spin (no nanosleep: sleep quantization
// cost ~us per wake was the R7 regression). All GRID blocks co-resident.
__device__ __forceinline__ void grid_barrier() {
    __syncthreads();
    if (threadIdx.x == 0) {
        __threadfence();                               // release prior writes
        unsigned gen = *(volatile unsigned*)&g_bar_gen;
        if (atomicAdd(&g_bar_arrive, 1u) == GRID - 1) {
            g_bar_arrive = 0;
            __threadfence();
            *(volatile unsigned*)&g_bar_gen = gen + 1; // wake
        } else {
            while (*(volatile unsigned*)&g_bar_gen == gen) {}
        }
        __threadfence();                               // acquire
    }
    __syncthreads();
}

#define TW 32
#define TH 8
#define SW (TW + 4)
#define SH (TH + 4)
#define NTILES ((Ww/TW)*(Hh/TH))   // 1440
#define NPB (HW/BT)                // 1440 pixel-blocks for final

__global__ void __launch_bounds__(BT, 5) k_render(
        const float* __restrict__ pts,
        const float* __restrict__ color,
        const float* __restrict__ imw,
        const int*   __restrict__ mask,
        const float* __restrict__ thresh,
        float* __restrict__ out_depth,
        float* __restrict__ out_color,
        float* __restrict__ out_imw,
        float* __restrict__ out_weight,
        float* __restrict__ out_vis,
        int n) {
    __shared__ union {
        unsigned int tile[SH * SW];   // patchmin
        float sc[BT * 3];             // final color staging
    } sm;

    const int tid  = threadIdx.x;
    const int gtid = blockIdx.x * BT + tid;

    // ================= phase 1: z-buffer scatter-min =================
    for (int i = gtid; i < n; i += NTHR) {
        float x = __ldg(&pts[3*i]), y = __ldg(&pts[3*i+1]), z = __ldg(&pts[3*i+2]);
        int px = __float2int_rd(x), py = __float2int_rd(y);
        bool valid = (px >= 0) & (px < Ww) & (py >= 0) & (py < Hh) & (mask[i] > 0);
        if (valid)
            atomicMax(&g_depth_key[py * Ww + px], ~__float_as_uint(z));
    }
    grid_barrier();

    // ====== phase 2: 5x5 patch-min + depth output + acc zeroing ======
    for (int t = blockIdx.x; t < NTILES; t += GRID) {
        int bx = t % (Ww / TW);
        int by = t / (Ww / TW);
        int x0 = bx * TW, y0 = by * TH;

        #pragma unroll
        for (int k = tid; k < SH * SW; k += BT) {
            int ly = k / SW, lx = k % SW;
            int gy = y0 + ly - 2, gx = x0 + lx - 2;
            unsigned v = 0u;
            if (gy >= 0 && gy < Hh && gx >= 0 && gx < Ww)
                v = __ldcg(&g_depth_key[gy * Ww + gx]);
            sm.tile[k] = v;
        }
        __syncthreads();

        int tx = tid % TW, ty = tid / TW;
        unsigned m = 0u;
        #pragma unroll
        for (int dy = 0; dy < 5; ++dy)
            #pragma unroll
            for (int dx = 0; dx < 5; ++dx)
                m = max(m, sm.tile[(ty + dy) * SW + (tx + dx)]);
        int gi = (y0 + ty) * Ww + (x0 + tx);
        g_patchmin[gi] = (m == 0u) ? BIGF : __uint_as_float(~m);
        unsigned ck = sm.tile[(ty + 2) * SW + (tx + 2)];
        out_depth[gi] = ck ? __uint_as_float(~ck) : 0.f;
        g_acc4[gi] = make_float4(0.f, 0.f, 0.f, 0.f);
        out_weight[gi] = 0.f;
        __syncthreads();   // protect tile before next iteration
    }
    grid_barrier();

    // ===== phase 3: visibility + 7x7 warp splat; also key reset =====
    {
        int lane = tid & 31;
        int u1 = lane + 32;
        int ox0 = lane % 7 - 3, oy0 = lane / 7 - 3;
        int ox1 = u1 % 7 - 3,   oy1 = u1 / 7 - 3;
        float cxo0 = (float)ox0 + 0.5f, cyo0 = (float)oy0 + 0.5f;
        float cxo1 = (float)ox1 + 0.5f, cyo1 = (float)oy1 + 0.5f;
        int ioff0 = oy0 * Ww + ox0;
        int ioff1 = oy1 * Ww + ox1;
        bool has1 = (u1 < 49);
        float th = __ldg(thresh);

        for (int i0 = gtid; i0 - lane < n; i0 += NTHR) {
            int i = i0;
            int warp_base = i - lane;
            bool vis = false;
            if (i < n) {
                float x = pts[3*i], y = pts[3*i+1], z = pts[3*i+2];
                int px = __float2int_rd(x), py = __float2int_rd(y);
                bool valid = (px >= 0) & (px < Ww) & (py >= 0) & (py < Hh) & (mask[i] > 0);
                int ccx = min(max(px, 0), Ww - 1);
                int ccy = min(max(py, 0), Hh - 1);
                float pm = __ldcg(&g_patchmin[ccy * Ww + ccx]);
                vis = valid && (z <= pm + th);
                out_vis[i] = vis ? 1.0f : 0.0f;
            }
            unsigned vm = __ballot_sync(0xffffffffu, vis);
            while (vm) {
                int src = __ffs(vm) - 1;
                vm &= vm - 1;
                int j = warp_base + src;     // warp-uniform broadcast loads
                float xx = __ldg(&pts[3*j]);
                float yy = __ldg(&pts[3*j+1]);
                float s0 = __ldg(&color[3*j]);
                float s1 = __ldg(&color[3*j+1]);
                float s2 = __ldg(&color[3*j+2]);
                float swv = __ldg(&imw[j]);
                int pxb = __float2int_rd(xx);
                int pyb = __float2int_rd(yy);
                float fx = (float)pxb - xx;
                float fy = (float)pyb - yy;
                int base = pyb * Ww + pxb;
                {
                    int sx = pxb + ox0, sy = pyb + oy0;
                    if (((unsigned)sx < Ww) & ((unsigned)sy < Hh)) {
                        float dx = fx + cxo0, dy = fy + cyo0;
                        float w = __fdividef(1.0f, fmaf(dx, dx, fmaf(dy, dy, EPSF)));
                        int idx = base + ioff0;
                        red_add_v4(&g_acc4[idx], w * s0, w * s1, w * s2, w * swv);
                        red_add_f32(&out_weight[idx], w);
                    }
                }
                if (has1) {
                    int sx = pxb + ox1, sy = pyb + oy1;
                    if (((unsigned)sx < Ww) & ((unsigned)sy < Hh)) {
                        float dx = fx + cxo1, dy = fy + cyo1;
                        float w = __fdividef(1.0f, fmaf(dx, dx, fmaf(dy, dy, EPSF)));
                        int idx = base + ioff1;
                        red_add_v4(&g_acc4[idx], w * s0, w * s1, w * s2, w * swv);
                        red_add_f32(&out_weight[idx], w);
                    }
                }
            }
        }
        // depth-key reset: splat never reads keys, patchmin is done => safe here,
        // overlaps the atomic-heavy splat with pure stores
        for (int i = gtid; i < HW; i += NTHR)
            g_depth_key[i] = 0u;
    }
    grid_barrier();

    // === phase 4: acc4 -> color/imw (smem-staged coalesced stores) ===
    for (int pb = blockIdx.x; pb < NPB; pb += GRID) {
        int i = pb * BT + tid;
        float4 a = __ldcg(&g_acc4[i]);
        sm.sc[tid * 3 + 0] = a.x;        // stride-3 smem: conflict-free
        sm.sc[tid * 3 + 1] = a.y;
        sm.sc[tid * 3 + 2] = a.z;
        out_imw[i] = a.w;
        __syncthreads();
        if (tid < 192)
            reinterpret_cast<float4*>(out_color)[pb * 192 + tid] =
                reinterpret_cast<const float4*>(sm.sc)[tid];
        __syncthreads();
    }
}

extern "C" void kernel_launch(void* const* d_in, const int* in_sizes, int n_in,
                              void* d_out, int out_size) {
    const float* pts    = (const float*)d_in[0];
    const float* color  = (const float*)d_in[1];
    const float* imw    = (const float*)d_in[2];
    const int*   mask   = (const int*)  d_in[3];
    const float* thresh = (const float*)d_in[4];
    int n = in_sizes[3];

    float* out = (float*)d_out;
    float* out_depth  = out;
    float* out_color  = out + HW;
    float* out_imw    = out + HW * 4;
    float* out_weight = out + HW * 5;
    float* out_vis    = out + HW * 6;

    k_render<<<GRID, BT>>>(pts, color, imw, mask, thresh,
                           out_depth, out_color, out_imw, out_weight, out_vis, n);
}

// round 9
// speedup vs baseline: 1.3384x; 1.3384x over previous
#include <cuda_runtime.h>
#include <cstdint>

#define Hh 576
#define Ww 640
#define HW (Hh*Ww)
#define BIGF 1e10f
#define EPSF 1e-5f

// ---- scratch (__device__ globals; zero-initialized at module load) ----
// Depth keys: key = ~bits(z); z>0 => key>0x80000000; key==0 means empty.
// min(z) = decode(max key). k_final resets keys to 0 (pure stores) => replay invariant.
__device__ unsigned int g_depth_key[HW];
__device__ float        g_patchmin[HW];
__device__ float4       g_acc4[HW];

__device__ __forceinline__ void red_add_v4(float4* p, float a, float b, float c, float d) {
    asm volatile("red.global.add.v4.f32 [%0], {%1,%2,%3,%4};"
                 :: "l"(__cvta_generic_to_global(p)),
                    "f"(a), "f"(b), "f"(c), "f"(d) : "memory");
}
__device__ __forceinline__ void red_add_f32(float* p, float v) {
    asm volatile("red.global.add.f32 [%0], %1;"
                 :: "l"(__cvta_generic_to_global(p)), "f"(v) : "memory");
}

// ---- k1: z-buffer scatter-min (complement-key atomicMax), 1 pt/thread ----
__global__ void k_zmin(const float* __restrict__ pts, const int* __restrict__ mask, int n) {
    int i = blockIdx.x * blockDim.x + threadIdx.x;
    if (i >= n) return;
    float x = __ldg(&pts[3*i]), y = __ldg(&pts[3*i+1]), z = __ldg(&pts[3*i+2]);
    int px = __float2int_rd(x), py = __float2int_rd(y);
    bool valid = (px >= 0) & (px < Ww) & (py >= 0) & (py < Hh) & (mask[i] > 0);
    if (valid)
        atomicMax(&g_depth_key[py * Ww + px], ~__float_as_uint(z));
}

// ---- k2: 5x5 patch-min (smem key-max) + depth output + accumulator zeroing ----
#define TW 32
#define TH 8
#define SW (TW + 4)
#define SH (TH + 4)
__global__ void k_patchmin(float* __restrict__ out_weight,
                           float* __restrict__ out_depth) {
    __shared__ unsigned int tile[SH * SW];
    int tid = threadIdx.x;
    int bx = blockIdx.x % (Ww / TW);
    int by = blockIdx.x / (Ww / TW);
    int x0 = bx * TW, y0 = by * TH;

    #pragma unroll
    for (int k = tid; k < SH * SW; k += 256) {
        int ly = k / SW, lx = k % SW;
        int gy = y0 + ly - 2, gx = x0 + lx - 2;
        unsigned v = 0u;  // empty (BIG depth)
        if (gy >= 0 && gy < Hh && gx >= 0 && gx < Ww)
            v = g_depth_key[gy * Ww + gx];
        tile[k] = v;
    }
    __syncthreads();

    int tx = tid % TW, ty = tid / TW;
    unsigned m = 0u;
    #pragma unroll
    for (int dy = 0; dy < 5; ++dy) {
        #pragma unroll
        for (int dx = 0; dx < 5; ++dx)
            m = max(m, tile[(ty + dy) * SW + (tx + dx)]);
    }
    int gi = (y0 + ty) * Ww + (x0 + tx);
    g_patchmin[gi] = (m == 0u) ? BIGF : __uint_as_float(~m);

    unsigned ck = tile[(ty + 2) * SW + (tx + 2)];
    out_depth[gi] = ck ? __uint_as_float(~ck) : 0.f;

    g_acc4[gi] = make_float4(0.f, 0.f, 0.f, 0.f);
    out_weight[gi] = 0.f;
}

// ---- k3: visibility + warp-cooperative 7x7 splat (uniform-load broadcast) ----
__global__ void __launch_bounds__(256) k_splat(
                        const float* __restrict__ pts,
                        const float* __restrict__ color,
                        const float* __restrict__ imw,
                        const int*   __restrict__ mask,
                        const float* __restrict__ thresh,
                        float* __restrict__ out_weight,
                        float* __restrict__ out_vis,
                        int n) {
    int i = blockIdx.x * blockDim.x + threadIdx.x;
    int lane = threadIdx.x & 31;
    int warp_base = i - lane;

    int u1 = lane + 32;
    int ox0 = lane % 7 - 3, oy0 = lane / 7 - 3;
    int ox1 = u1 % 7 - 3,   oy1 = u1 / 7 - 3;
    float cxo0 = (float)ox0 + 0.5f, cyo0 = (float)oy0 + 0.5f;
    float cxo1 = (float)ox1 + 0.5f, cyo1 = (float)oy1 + 0.5f;
    int ioff0 = oy0 * Ww + ox0;
    int ioff1 = oy1 * Ww + ox1;
    bool has1 = (u1 < 49);

    bool vis = false;
    if (i < n) {
        float x = pts[3*i], y = pts[3*i+1], z = pts[3*i+2];
        int px = __float2int_rd(x), py = __float2int_rd(y);
        bool valid = (px >= 0) & (px < Ww) & (py >= 0) & (py < Hh) & (mask[i] > 0);
        int ccx = min(max(px, 0), Ww - 1);
        int ccy = min(max(py, 0), Hh - 1);
        float pm = g_patchmin[ccy * Ww + ccx];
        float th = __ldg(thresh);
        vis = valid && (z <= pm + th);
        out_vis[i] = vis ? 1.0f : 0.0f;
    }

    unsigned vm = __ballot_sync(0xffffffffu, vis);
    while (vm) {
        int src = __ffs(vm) - 1;
        vm &= vm - 1;
        int j = warp_base + src;              // warp-uniform -> broadcast loads
        float xx = __ldg(&pts[3*j]);
        float yy = __ldg(&pts[3*j+1]);
        float s0 = __ldg(&color[3*j]);
        float s1 = __ldg(&color[3*j+1]);
        float s2 = __ldg(&color[3*j+2]);
        float swv = __ldg(&imw[j]);
        int pxb = __float2int_rd(xx);
        int pyb = __float2int_rd(yy);
        float fx = (float)pxb - xx;
        float fy = (float)pyb - yy;
        int base = pyb * Ww + pxb;

        {
            int sx = pxb + ox0, sy = pyb + oy0;
            if (((unsigned)sx < Ww) & ((unsigned)sy < Hh)) {
                float dx = fx + cxo0, dy = fy + cyo0;
                float w = __fdividef(1.0f, fmaf(dx, dx, fmaf(dy, dy, EPSF)));
                int idx = base + ioff0;
                red_add_v4(&g_acc4[idx], w * s0, w * s1, w * s2, w * swv);
                red_add_f32(&out_weight[idx], w);
            }
        }
        if (has1) {
            int sx = pxb + ox1, sy = pyb + oy1;
            if (((unsigned)sx < Ww) & ((unsigned)sy < Hh)) {
                float dx = fx + cxo1, dy = fy + cyo1;
                float w = __fdividef(1.0f, fmaf(dx, dx, fmaf(dy, dy, EPSF)));
                int idx = base + ioff1;
                red_add_v4(&g_acc4[idx], w * s0, w * s1, w * s2, w * swv);
                red_add_f32(&out_weight[idx], w);
            }
        }
    }
}

// ---- k4: acc4 -> color/imw. Block=64 threads, 4 px/thread (MLP=4), grid=1440.
//      Block covers 256 contiguous pixels; color staged in smem for coalesced
//      float4 stores. Depth-key reset = pure stores (replay invariant). ----
#define FB 64
__global__ void __launch_bounds__(FB) k_final(float* __restrict__ out_color,
                                              float* __restrict__ out_imw) {
    __shared__ float sc[256 * 3];
    int tid = threadIdx.x;
    int base = blockIdx.x * 256;

    // 4 independent 16B loads issued back-to-back (MLP=4), coalesced per warp
    float4 a0 = __ldcg(&g_acc4[base + tid]);
    float4 a1 = __ldcg(&g_acc4[base + tid + 64]);
    float4 a2 = __ldcg(&g_acc4[base + tid + 128]);
    float4 a3 = __ldcg(&g_acc4[base + tid + 192]);

    sc[(tid      ) * 3 + 0] = a0.x; sc[(tid      ) * 3 + 1] = a0.y; sc[(tid      ) * 3 + 2] = a0.z;
    sc[(tid +  64) * 3 + 0] = a1.x; sc[(tid +  64) * 3 + 1] = a1.y; sc[(tid +  64) * 3 + 2] = a1.z;
    sc[(tid + 128) * 3 + 0] = a2.x; sc[(tid + 128) * 3 + 1] = a2.y; sc[(tid + 128) * 3 + 2] = a2.z;
    sc[(tid + 192) * 3 + 0] = a3.x; sc[(tid + 192) * 3 + 1] = a3.y; sc[(tid + 192) * 3 + 2] = a3.z;

    out_imw[base + tid]       = a0.w;
    out_imw[base + tid +  64] = a1.w;
    out_imw[base + tid + 128] = a2.w;
    out_imw[base + tid + 192] = a3.w;

    // reset depth keys for next replay (pure stores, coalesced)
    g_depth_key[base + tid]       = 0u;
    g_depth_key[base + tid +  64] = 0u;
    g_depth_key[base + tid + 128] = 0u;
    g_depth_key[base + tid + 192] = 0u;

    __syncthreads();
    float4* oc = reinterpret_cast<float4*>(out_color) + blockIdx.x * 192;
    const float4* s4 = reinterpret_cast<const float4*>(sc);
    oc[tid]       = s4[tid];
    oc[tid +  64] = s4[tid + 64];
    oc[tid + 128] = s4[tid + 128];
}

extern "C" void kernel_launch(void* const* d_in, const int* in_sizes, int n_in,
                              void* d_out, int out_size) {
    const float* pts    = (const float*)d_in[0];
    const float* color  = (const float*)d_in[1];
    const float* imw    = (const float*)d_in[2];
    const int*   mask   = (const int*)  d_in[3];
    const float* thresh = (const float*)d_in[4];
    int n = in_sizes[3];

    float* out = (float*)d_out;
    float* out_depth  = out;
    float* out_color  = out + HW;
    float* out_imw    = out + HW * 4;
    float* out_weight = out + HW * 5;
    float* out_vis    = out + HW * 6;

    const int BT = 256;
    int gp  = (n + BT - 1) / BT;          // 782
    int gt  = (Ww / TW) * (Hh / TH);      // 1440
    int gf  = HW / 256;                   // 1440 blocks of 64 threads

    k_zmin<<<gp, BT>>>(pts, mask, n);
    k_patchmin<<<gt, BT>>>(out_weight, out_depth);
    k_splat<<<gp, BT>>>(pts, color, imw, mask, thresh, out_weight, out_vis, n);
    k_final<<<gf, FB>>>(out_color, out_imw);
}